// round 2
// baseline (speedup 1.0000x reference)
#include <cuda_runtime.h>

#define BB 4
#define NN 16384
#define MM 2048
#define CC 64
#define KK 32
#define ROW 68            // xyz, pad, 64 features
#define R2C 0.01f

// Transposed scratch: [b][n][0..2] = xyz, [3] = pad, [4..67] = features
__device__ float g_t[(size_t)BB * NN * ROW];

// ---------------------------------------------------------------------------
// Pre-pass: transpose (B,3,N) coords + (B,C,N) features into (B,N,ROW) rows
// ---------------------------------------------------------------------------
__global__ void __launch_bounds__(256) transpose_kernel(
    const float* __restrict__ pc, const float* __restrict__ pf)
{
    __shared__ float tile[67][65];
    int b  = blockIdx.y;
    int n0 = blockIdx.x * 64;

    const float* src_c = pc + (size_t)b * 3 * NN;
    const float* src_f = pf + (size_t)b * CC * NN;

    // coalesced loads along n
    for (int i = threadIdx.x; i < 67 * 64; i += 256) {
        int c  = i >> 6;
        int nl = i & 63;
        float v = (c < 3) ? src_c[(size_t)c * NN + n0 + nl]
                          : src_f[(size_t)(c - 3) * NN + n0 + nl];
        tile[c][nl] = v;
    }
    __syncthreads();

    // coalesced stores along the ROW dimension
    float* dst = g_t + ((size_t)b * NN + n0) * ROW;
    for (int i = threadIdx.x; i < 68 * 64; i += 256) {
        int nl = i / 68;
        int j  = i % 68;
        float v;
        if (j < 3)       v = tile[j][nl];
        else if (j == 3) v = 0.0f;
        else             v = tile[j - 1][nl];
        dst[i] = v;   // dst[nl*ROW + j]
    }
}

// ---------------------------------------------------------------------------
// Main kernel: warp-per-center ball query (early exit) + fused grouping
// ---------------------------------------------------------------------------
__device__ __forceinline__ bool bq_hit(float px, float py, float pz,
                                       float cx, float cy, float cz, float c2)
{
    // Match reference numerics:
    //   p2    = (px*px + py*py) + pz*pz        (XLA mul + sequential reduce)
    //   inner = fma(cz,pz, fma(cy,py, cx*px))  (cuBLAS k=3 FMA chain)
    //   d2    = (c2 + p2) - 2*inner
    float p2    = __fadd_rn(__fadd_rn(__fmul_rn(px, px), __fmul_rn(py, py)),
                            __fmul_rn(pz, pz));
    float inner = __fmaf_rn(cz, pz, __fmaf_rn(cy, py, __fmul_rn(cx, px)));
    float d2    = __fsub_rn(__fadd_rn(c2, p2), __fmul_rn(2.0f, inner));
    return d2 < R2C;
}

__global__ void __launch_bounds__(256) ballquery_kernel(
    const float* __restrict__ pc, const float* __restrict__ cc,
    float* __restrict__ out)
{
    int gw   = blockIdx.x * 8 + (threadIdx.x >> 5);   // global warp = center id
    int lane = threadIdx.x & 31;
    int b = gw / MM;
    int m = gw % MM;

    const float4* x4 = (const float4*)(pc + (size_t)b * 3 * NN);
    const float4* y4 = x4 + NN / 4;
    const float4* z4 = y4 + NN / 4;

    const float* cb = cc + (size_t)b * 3 * MM;
    float cx = cb[m], cy = cb[MM + m], cz = cb[2 * MM + m];
    float c2 = __fadd_rn(__fadd_rn(__fmul_rn(cx, cx), __fmul_rn(cy, cy)),
                         __fmul_rn(cz, cz));

    int cnt   = 0;
    int myidx = 0;   // lane L holds neighbor index for slot k = L

    // 128 points per warp-step: lane covers float4 at (base+lane)
    for (int base = 0; base < NN / 4 && cnt < KK; base += 32) {
        float4 xv = __ldg(x4 + base + lane);
        float4 yv = __ldg(y4 + base + lane);
        float4 zv = __ldg(z4 + base + lane);

        unsigned hm = 0;
        hm |= bq_hit(xv.x, yv.x, zv.x, cx, cy, cz, c2) ? 1u : 0u;
        hm |= bq_hit(xv.y, yv.y, zv.y, cx, cy, cz, c2) ? 2u : 0u;
        hm |= bq_hit(xv.z, yv.z, zv.z, cx, cy, cz, c2) ? 4u : 0u;
        hm |= bq_hit(xv.w, yv.w, zv.w, cx, cy, cz, c2) ? 8u : 0u;

        unsigned wm = __ballot_sync(0xffffffffu, hm != 0u);
        // sparse: avg ~0.5 hits per 128-point step; extract in ascending order
        while (wm && cnt < KK) {
            int src = __ffs(wm) - 1;
            wm &= wm - 1;
            unsigned h = __shfl_sync(0xffffffffu, hm, src);
            int nb = (base + src) * 4;
            while (h && cnt < KK) {
                int bit = __ffs(h) - 1;
                h &= h - 1;
                if (lane == cnt) myidx = nb + bit;
                cnt++;
            }
        }
    }

    // pad slots >= cnt with first hit (or 0 if no hits)
    int first = __shfl_sync(0xffffffffu, myidx, 0);
    if (cnt == 0) first = 0;
    if (lane >= cnt) myidx = first;

    // ---- fused grouping: lane = output slot k, reads its neighbor's row ----
    const float* row = g_t + ((size_t)b * NN + myidx) * ROW;
    float4 xyz = *(const float4*)row;

    const size_t CH = (size_t)MM * KK;                     // per-channel stride
    size_t ob = (((size_t)b * 67) * MM + m) * KK + lane;   // channel 0

    out[ob]          = __fsub_rn(xyz.x, cx);
    out[ob + CH]     = __fsub_rn(xyz.y, cy);
    out[ob + 2 * CH] = __fsub_rn(xyz.z, cz);

    const float4* r4 = (const float4*)(row + 4);
    #pragma unroll
    for (int q = 0; q < 16; q++) {
        float4 v = __ldg(r4 + q);
        size_t o = ob + (size_t)(3 + q * 4) * CH;
        out[o]          = v.x;
        out[o + CH]     = v.y;
        out[o + 2 * CH] = v.z;
        out[o + 3 * CH] = v.w;
    }
}

// ---------------------------------------------------------------------------
extern "C" void kernel_launch(void* const* d_in, const int* in_sizes, int n_in,
                              void* d_out, int out_size)
{
    const float* pc = (const float*)d_in[0];   // points_coords  (B,3,N)
    const float* cc = (const float*)d_in[1];   // centers_coords (B,3,M)
    const float* pf = (const float*)d_in[2];   // points_features(B,C,N)
    float* out = (float*)d_out;                // (B, 67, M, K)

    dim3 tgrid(NN / 64, BB);
    transpose_kernel<<<tgrid, 256>>>(pc, pf);

    ballquery_kernel<<<BB * MM / 8, 256>>>(pc, cc, out);
}

// round 3
// speedup vs baseline: 1.5825x; 1.5825x over previous
#include <cuda_runtime.h>

#define BB 4
#define NN 16384
#define MM 2048
#define CC 64
#define KK 32
#define ROW 68            // xyz, pad, 64 features
#define R2C 0.01f
#define GC 10
#define NCELL 1000
#define IMAX 0x7fffffff

// Transposed rows for grouping gather: [b][n][0..2]=xyz, [3]=pad, [4..67]=features
__device__ __align__(16) float g_t[(size_t)BB * NN * ROW];
// Grid-binned points: (x,y,z,p2) + original index
__device__ __align__(16) float4 g_bpt[BB * NN];
__device__ int g_bidx[BB * NN];
__device__ int g_cnt[BB * NCELL];
__device__ int g_start[BB * (NCELL + 1)];
__device__ int g_cursor[BB * NCELL];

__device__ __forceinline__ int cell_of(float x) {
    int c = (int)(x * 10.0f);
    return c < 0 ? 0 : (c > 9 ? 9 : c);
}

// ---------------------------------------------------------------------------
// K1: transpose (B,3,N)+(B,C,N) -> (B,N,68) rows; also zero the histogram
// ---------------------------------------------------------------------------
__global__ void __launch_bounds__(256) transpose_kernel(
    const float* __restrict__ pc, const float* __restrict__ pf)
{
    __shared__ float tile[67][65];
    int b  = blockIdx.y;
    int n0 = blockIdx.x * 64;

    if (b == 0 && blockIdx.x < 16) {
        int t = blockIdx.x * 256 + threadIdx.x;
        if (t < BB * NCELL) g_cnt[t] = 0;
    }

    const float* src_c = pc + (size_t)b * 3 * NN;
    const float* src_f = pf + (size_t)b * CC * NN;

    // float4 loads along n
    for (int i = threadIdx.x; i < 67 * 16; i += 256) {
        int c = i >> 4, q = i & 15;
        const float* s = (c < 3) ? (src_c + (size_t)c * NN)
                                 : (src_f + (size_t)(c - 3) * NN);
        float4 v = *(const float4*)(s + n0 + q * 4);
        tile[c][q * 4 + 0] = v.x; tile[c][q * 4 + 1] = v.y;
        tile[c][q * 4 + 2] = v.z; tile[c][q * 4 + 3] = v.w;
    }
    __syncthreads();

    // float4 stores along the 68-float row (row = 272B, 16B aligned)
    float* dst = g_t + ((size_t)b * NN + n0) * ROW;
    for (int i = threadIdx.x; i < 64 * 17; i += 256) {
        int nl = i / 17, q = i % 17;
        float4 v;
        if (q == 0) { v.x = tile[0][nl]; v.y = tile[1][nl]; v.z = tile[2][nl]; v.w = 0.0f; }
        else { v.x = tile[4*q-1][nl]; v.y = tile[4*q][nl]; v.z = tile[4*q+1][nl]; v.w = tile[4*q+2][nl]; }
        *(float4*)(dst + (size_t)nl * ROW + q * 4) = v;
    }
}

// ---------------------------------------------------------------------------
// K2: per-cell histogram
// ---------------------------------------------------------------------------
__global__ void __launch_bounds__(256) count_kernel(const float* __restrict__ pc)
{
    int t = blockIdx.x * 256 + threadIdx.x;
    if (t >= BB * NN) return;
    int b = t / NN, n = t % NN;
    const float* base = pc + (size_t)b * 3 * NN;
    float x = base[n], y = base[NN + n], z = base[2 * NN + n];
    int cell = (cell_of(x) * GC + cell_of(y)) * GC + cell_of(z);
    atomicAdd(&g_cnt[b * NCELL + cell], 1);
}

// ---------------------------------------------------------------------------
// K3: exclusive scan per batch (1 block/batch)
// ---------------------------------------------------------------------------
__global__ void __launch_bounds__(1024) scan_kernel()
{
    __shared__ int s[NCELL];
    int b = blockIdx.x, t = threadIdx.x;
    int myc = 0;
    if (t < NCELL) { myc = g_cnt[b * NCELL + t]; s[t] = myc; }
    __syncthreads();
    for (int off = 1; off < NCELL; off <<= 1) {
        int v = 0;
        if (t < NCELL && t >= off) v = s[t - off];
        __syncthreads();
        if (t < NCELL) s[t] += v;
        __syncthreads();
    }
    if (t < NCELL) {
        int excl = s[t] - myc;
        g_start[b * (NCELL + 1) + t] = excl;
        g_cursor[b * NCELL + t]      = excl;
    }
    if (t == 0) g_start[b * (NCELL + 1) + NCELL] = NN;
}

// ---------------------------------------------------------------------------
// K4: scatter points into bins (order within cell arbitrary; final sort fixes)
// ---------------------------------------------------------------------------
__global__ void __launch_bounds__(256) scatter_kernel(const float* __restrict__ pc)
{
    int t = blockIdx.x * 256 + threadIdx.x;
    if (t >= BB * NN) return;
    int b = t / NN, n = t % NN;
    const float* base = pc + (size_t)b * 3 * NN;
    float x = base[n], y = base[NN + n], z = base[2 * NN + n];
    // reference p2: (x*x + y*y) + z*z, individually rounded
    float p2 = __fadd_rn(__fadd_rn(__fmul_rn(x, x), __fmul_rn(y, y)),
                         __fmul_rn(z, z));
    int cell = (cell_of(x) * GC + cell_of(y)) * GC + cell_of(z);
    int pos = atomicAdd(&g_cursor[b * NCELL + cell], 1);
    g_bpt[b * NN + pos]  = make_float4(x, y, z, p2);
    g_bidx[b * NN + pos] = n;
}

// ---------------------------------------------------------------------------
// Bitonic sort helpers: 128 elems, element e = eBase + lane, reg eBase = 0/32/64/96
// ---------------------------------------------------------------------------
__device__ __forceinline__ void xstage(int& h, int eBase, int lane, int j, int k)
{
    int o = __shfl_xor_sync(0xffffffffu, h, j);
    int e = eBase + lane;
    bool asc   = (e & k) == 0;
    bool lower = (e & j) == 0;
    h = (lower == asc) ? min(h, o) : max(h, o);
}
__device__ __forceinline__ void rstage(int& a, int& b, int eBaseA, int lane, int k)
{
    bool asc = ((eBaseA + lane) & k) == 0;
    int mn = min(a, b), mx = max(a, b);
    a = asc ? mn : mx;
    b = asc ? mx : mn;
}
#define XS(j, k) { xstage(h0, 0, lane, j, k); xstage(h1, 32, lane, j, k); \
                   xstage(h2, 64, lane, j, k); xstage(h3, 96, lane, j, k); }

// ---------------------------------------------------------------------------
// K5: warp-per-center grid ball query + sort + fused grouping
// ---------------------------------------------------------------------------
__global__ void __launch_bounds__(256) query_kernel(
    const float* __restrict__ cc, float* __restrict__ out)
{
    int gw   = blockIdx.x * 8 + (threadIdx.x >> 5);
    int lane = threadIdx.x & 31;
    int b = gw / MM;
    int m = gw % MM;

    const float* cb = cc + (size_t)b * 3 * MM;
    float cx = cb[m], cy = cb[MM + m], cz = cb[2 * MM + m];
    float c2 = __fadd_rn(__fadd_rn(__fmul_rn(cx, cx), __fmul_rn(cy, cy)),
                         __fmul_rn(cz, cz));

    int ci = cell_of(cx), cj = cell_of(cy), ck = cell_of(cz);
    int i0 = max(ci - 1, 0), i1 = min(ci + 1, 9);
    int j0 = max(cj - 1, 0), j1 = min(cj + 1, 9);
    int k0 = max(ck - 1, 0), k1 = min(ck + 1, 9);

    const float4* bpt = g_bpt + (size_t)b * NN;
    const int* bidx   = g_bidx + (size_t)b * NN;
    const int* st     = g_start + b * (NCELL + 1);

    int h0 = IMAX, h1 = IMAX, h2 = IMAX, h3 = IMAX;
    int cnt = 0;

    for (int i = i0; i <= i1; i++) {
        for (int j = j0; j <= j1; j++) {
            int cbase = (i * GC + j) * GC;
            int s = st[cbase + k0];
            int e = st[cbase + k1 + 1];     // k-range is contiguous
            for (int p0 = s; p0 < e; p0 += 32) {
                int p = p0 + lane;
                bool hit = false;
                int hidx = 0;
                if (p < e) {
                    float4 v = __ldg(bpt + p);
                    float inner = __fmaf_rn(cz, v.z,
                                  __fmaf_rn(cy, v.y, __fmul_rn(cx, v.x)));
                    float d2 = __fsub_rn(__fadd_rn(c2, v.w),
                                         __fmul_rn(2.0f, inner));
                    hit = d2 < R2C;
                }
                unsigned wm = __ballot_sync(0xffffffffu, hit);
                if (hit) hidx = __ldg(bidx + p);
                while (wm) {
                    int src = __ffs(wm) - 1;
                    wm &= wm - 1;
                    int ix = __shfl_sync(0xffffffffu, hidx, src);
                    int reg = cnt >> 5;
                    if (lane == (cnt & 31)) {
                        if (reg == 0) h0 = ix;
                        else if (reg == 1) h1 = ix;
                        else if (reg == 2) h2 = ix;
                        else if (reg == 3) h3 = ix;
                    }
                    cnt++;
                }
            }
        }
    }

    // ---- bitonic sort of 128 (pads = IMAX) ----
    XS(1, 2)
    XS(2, 4)  XS(1, 4)
    XS(4, 8)  XS(2, 8)  XS(1, 8)
    XS(8, 16) XS(4, 16) XS(2, 16) XS(1, 16)
    XS(16, 32) XS(8, 32) XS(4, 32) XS(2, 32) XS(1, 32)
    rstage(h0, h1, 0, lane, 64); rstage(h2, h3, 64, lane, 64);
    XS(16, 64) XS(8, 64) XS(4, 64) XS(2, 64) XS(1, 64)
    rstage(h0, h2, 0, lane, 128); rstage(h1, h3, 32, lane, 128);
    rstage(h0, h1, 0, lane, 128); rstage(h2, h3, 64, lane, 128);
    XS(16, 128) XS(8, 128) XS(4, 128) XS(2, 128) XS(1, 128)

    // slot k = lane gets k-th smallest = h0; pad with first hit (or 0)
    int myidx = h0;
    int first = __shfl_sync(0xffffffffu, h0, 0);
    if (first == IMAX) first = 0;
    if (myidx == IMAX) myidx = first;

    // ---- fused grouping: lane = output slot k ----
    const float* row = g_t + ((size_t)b * NN + myidx) * ROW;
    float4 xyz = *(const float4*)row;

    const size_t CH = (size_t)MM * KK;
    size_t ob = (((size_t)b * 67) * MM + m) * KK + lane;

    out[ob]          = __fsub_rn(xyz.x, cx);
    out[ob + CH]     = __fsub_rn(xyz.y, cy);
    out[ob + 2 * CH] = __fsub_rn(xyz.z, cz);

    const float4* r4 = (const float4*)(row + 4);
    #pragma unroll
    for (int q = 0; q < 16; q++) {
        float4 v = __ldg(r4 + q);
        size_t o = ob + (size_t)(3 + q * 4) * CH;
        out[o]          = v.x;
        out[o + CH]     = v.y;
        out[o + 2 * CH] = v.z;
        out[o + 3 * CH] = v.w;
    }
}

// ---------------------------------------------------------------------------
extern "C" void kernel_launch(void* const* d_in, const int* in_sizes, int n_in,
                              void* d_out, int out_size)
{
    const float* pc = (const float*)d_in[0];   // points_coords  (B,3,N)
    const float* cc = (const float*)d_in[1];   // centers_coords (B,3,M)
    const float* pf = (const float*)d_in[2];   // points_features(B,C,N)
    float* out = (float*)d_out;                // (B, 67, M, K)

    dim3 tgrid(NN / 64, BB);
    transpose_kernel<<<tgrid, 256>>>(pc, pf);
    count_kernel<<<(BB * NN) / 256, 256>>>(pc);
    scan_kernel<<<BB, 1024>>>();
    scatter_kernel<<<(BB * NN) / 256, 256>>>(pc);
    query_kernel<<<BB * MM / 8, 256>>>(cc, out);
}

// round 4
// speedup vs baseline: 2.1006x; 1.3274x over previous
#include <cuda_runtime.h>

#define BB 4
#define NN 16384
#define MM 2048
#define CC 64
#define KK 32
#define ROW 68            // xyz, pad, 64 features
#define R2C 0.01f
#define GC 10
#define NCELL 1000
#define IMAX 0x7fffffff

// Transposed rows for grouping gather: [b][n][0..2]=xyz, [3]=pad, [4..67]=features
__device__ __align__(16) float g_t[(size_t)BB * NN * ROW];
// Grid-binned points: (x, y, z, index-as-float-bits)
__device__ __align__(16) float4 g_bpt[BB * NN];
__device__ int g_cnt[BB * NCELL];          // zero-init; re-zeroed by scan_kernel
__device__ int g_start[BB * (NCELL + 1)];
__device__ int g_cursor[BB * NCELL];

__device__ __forceinline__ int cell_of(float x) {
    int c = (int)(x * 10.0f);
    return c < 0 ? 0 : (c > 9 ? 9 : c);
}

// ---------------------------------------------------------------------------
// K1: transpose (B,3,N)+(B,C,N) -> (B,N,68) rows; fused per-cell histogram
// ---------------------------------------------------------------------------
__global__ void __launch_bounds__(256) transpose_kernel(
    const float* __restrict__ pc, const float* __restrict__ pf)
{
    __shared__ float tile[67][65];
    int b  = blockIdx.y;
    int n0 = blockIdx.x * 64;

    const float* src_c = pc + (size_t)b * 3 * NN;
    const float* src_f = pf + (size_t)b * CC * NN;

    // float4 loads along n
    for (int i = threadIdx.x; i < 67 * 16; i += 256) {
        int c = i >> 4, q = i & 15;
        const float* s = (c < 3) ? (src_c + (size_t)c * NN)
                                 : (src_f + (size_t)(c - 3) * NN);
        float4 v = *(const float4*)(s + n0 + q * 4);
        tile[c][q * 4 + 0] = v.x; tile[c][q * 4 + 1] = v.y;
        tile[c][q * 4 + 2] = v.z; tile[c][q * 4 + 3] = v.w;
    }
    __syncthreads();

    // fused histogram: 64 points of this block
    if (threadIdx.x < 64) {
        int t = threadIdx.x;
        float x = tile[0][t], y = tile[1][t], z = tile[2][t];
        int cell = (cell_of(x) * GC + cell_of(y)) * GC + cell_of(z);
        atomicAdd(&g_cnt[b * NCELL + cell], 1);
    }

    // float4 stores along the 68-float row (row = 272B, 16B aligned)
    float* dst = g_t + ((size_t)b * NN + n0) * ROW;
    for (int i = threadIdx.x; i < 64 * 17; i += 256) {
        int nl = i / 17, q = i % 17;
        float4 v;
        if (q == 0) { v.x = tile[0][nl]; v.y = tile[1][nl]; v.z = tile[2][nl]; v.w = 0.0f; }
        else { v.x = tile[4*q-1][nl]; v.y = tile[4*q][nl]; v.z = tile[4*q+1][nl]; v.w = tile[4*q+2][nl]; }
        *(float4*)(dst + (size_t)nl * ROW + q * 4) = v;
    }
}

// ---------------------------------------------------------------------------
// K2: exclusive scan per batch (1 block/batch); re-zeroes g_cnt for next run
// ---------------------------------------------------------------------------
__global__ void __launch_bounds__(1024) scan_kernel()
{
    __shared__ int s[NCELL];
    int b = blockIdx.x, t = threadIdx.x;
    int myc = 0;
    if (t < NCELL) {
        myc = g_cnt[b * NCELL + t];
        g_cnt[b * NCELL + t] = 0;      // restore invariant for next replay
        s[t] = myc;
    }
    __syncthreads();
    for (int off = 1; off < NCELL; off <<= 1) {
        int v = 0;
        if (t < NCELL && t >= off) v = s[t - off];
        __syncthreads();
        if (t < NCELL) s[t] += v;
        __syncthreads();
    }
    if (t < NCELL) {
        int excl = s[t] - myc;
        g_start[b * (NCELL + 1) + t] = excl;
        g_cursor[b * NCELL + t]      = excl;
    }
    if (t == 0) g_start[b * (NCELL + 1) + NCELL] = NN;
}

// ---------------------------------------------------------------------------
// K3: scatter points into bins (order within cell arbitrary; final select fixes)
// ---------------------------------------------------------------------------
__global__ void __launch_bounds__(256) scatter_kernel(const float* __restrict__ pc)
{
    int t = blockIdx.x * 256 + threadIdx.x;
    if (t >= BB * NN) return;
    int b = t / NN, n = t % NN;
    const float* base = pc + (size_t)b * 3 * NN;
    float x = base[n], y = base[NN + n], z = base[2 * NN + n];
    int cell = (cell_of(x) * GC + cell_of(y)) * GC + cell_of(z);
    int pos = atomicAdd(&g_cursor[b * NCELL + cell], 1);
    g_bpt[b * NN + pos] = make_float4(x, y, z, __int_as_float(n));
}

// ---------------------------------------------------------------------------
// Warp bitonic helpers (32 elems across lanes)
// ---------------------------------------------------------------------------
__device__ __forceinline__ void bstage(int& h, int lane, int j, int k)
{
    int o = __shfl_xor_sync(0xffffffffu, h, j);
    bool asc   = (lane & k) == 0;
    bool lower = (lane & j) == 0;
    h = (lower == asc) ? min(h, o) : max(h, o);
}
__device__ __forceinline__ void sort32(int& h, int lane)
{
    bstage(h, lane, 1, 2);
    bstage(h, lane, 2, 4);  bstage(h, lane, 1, 4);
    bstage(h, lane, 4, 8);  bstage(h, lane, 2, 8);  bstage(h, lane, 1, 8);
    bstage(h, lane, 8, 16); bstage(h, lane, 4, 16); bstage(h, lane, 2, 16); bstage(h, lane, 1, 16);
    bstage(h, lane, 16, 32); bstage(h, lane, 8, 32); bstage(h, lane, 4, 32);
    bstage(h, lane, 2, 32);  bstage(h, lane, 1, 32);
}
// clean a bitonic sequence into ascending order
__device__ __forceinline__ void clean32(int& h, int lane)
{
    #pragma unroll
    for (int j = 16; j >= 1; j >>= 1) {
        int o = __shfl_xor_sync(0xffffffffu, h, j);
        h = ((lane & j) == 0) ? min(h, o) : max(h, o);
    }
}
// keep 32 smallest of two ascending-sorted 32-seqs, result ascending in a
__device__ __forceinline__ void merge_min32(int& a, int b, int lane)
{
    int br = __shfl_sync(0xffffffffu, b, 31 ^ lane);  // b reversed
    a = min(a, br);                                   // bitonic
    clean32(a, lane);
}

// ---------------------------------------------------------------------------
// K4: warp-per-center grid ball query + top-32 select + fused grouping
// ---------------------------------------------------------------------------
__global__ void __launch_bounds__(256) query_kernel(
    const float* __restrict__ cc, float* __restrict__ out)
{
    __shared__ int hits[8][128];
    int wib  = threadIdx.x >> 5;
    int lane = threadIdx.x & 31;
    int* hb  = hits[wib];

    int gw = blockIdx.x * 8 + wib;
    int b = gw / MM;
    int m = gw % MM;

    const float* cb = cc + (size_t)b * 3 * MM;
    float cx = cb[m], cy = cb[MM + m], cz = cb[2 * MM + m];
    float c2 = __fadd_rn(__fadd_rn(__fmul_rn(cx, cx), __fmul_rn(cy, cy)),
                         __fmul_rn(cz, cz));

    int ci = cell_of(cx), cj = cell_of(cy), ck = cell_of(cz);
    int i0 = max(ci - 1, 0), i1 = min(ci + 1, 9);
    int j0 = max(cj - 1, 0), j1 = min(cj + 1, 9);
    int k0 = max(ck - 1, 0), k1 = min(ck + 1, 9);

    const float4* bpt = g_bpt + (size_t)b * NN;
    const int* st     = g_start + b * (NCELL + 1);

    unsigned below = (1u << lane) - 1u;
    int cnt = 0;

    for (int i = i0; i <= i1; i++) {
        for (int j = j0; j <= j1; j++) {
            int cbase = (i * GC + j) * GC;
            int s = st[cbase + k0];
            int e = st[cbase + k1 + 1];     // k-range contiguous in bins
            for (int p0 = s; p0 < e; p0 += 32) {
                int p = p0 + lane;
                bool hit = false;
                float4 v;
                if (p < e) {
                    v = __ldg(bpt + p);
                    // reference p2: (x*x + y*y) + z*z, individually rounded
                    float p2 = __fadd_rn(__fadd_rn(__fmul_rn(v.x, v.x),
                                                   __fmul_rn(v.y, v.y)),
                                         __fmul_rn(v.z, v.z));
                    // reference inner: cuBLAS k=3 FMA chain
                    float inner = __fmaf_rn(cz, v.z,
                                  __fmaf_rn(cy, v.y, __fmul_rn(cx, v.x)));
                    float d2 = __fsub_rn(__fadd_rn(c2, p2),
                                         __fmul_rn(2.0f, inner));
                    hit = d2 < R2C;
                }
                unsigned wm = __ballot_sync(0xffffffffu, hit);
                if (hit) {
                    int rank = cnt + __popc(wm & below);
                    if (rank < 128) hb[rank] = __float_as_int(v.w);
                }
                cnt += __popc(wm);
            }
        }
    }
    __syncwarp();

    // load up to 128 collected hits (pads = IMAX)
    int h0 = (lane      < cnt) ? hb[lane]      : IMAX;
    int h1 = (lane + 32 < cnt) ? hb[lane + 32] : IMAX;
    int h2 = (lane + 64 < cnt) ? hb[lane + 64] : IMAX;
    int h3 = (lane + 96 < cnt) ? hb[lane + 96] : IMAX;

    // top-32 smallest (ascending) into h0
    sort32(h0, lane); sort32(h1, lane); sort32(h2, lane); sort32(h3, lane);
    merge_min32(h0, h1, lane);
    merge_min32(h2, h3, lane);
    merge_min32(h0, h2, lane);

    int myidx = h0;
    int first = __shfl_sync(0xffffffffu, h0, 0);
    if (first == IMAX) first = 0;
    if (myidx == IMAX) myidx = first;

    // ---- fused grouping: lane = output slot k ----
    const float* row = g_t + ((size_t)b * NN + myidx) * ROW;
    float4 xyz = *(const float4*)row;

    const size_t CH = (size_t)MM * KK;
    size_t ob = (((size_t)b * 67) * MM + m) * KK + lane;

    out[ob]          = __fsub_rn(xyz.x, cx);
    out[ob + CH]     = __fsub_rn(xyz.y, cy);
    out[ob + 2 * CH] = __fsub_rn(xyz.z, cz);

    const float4* r4 = (const float4*)(row + 4);
    #pragma unroll
    for (int q = 0; q < 16; q++) {
        float4 v = __ldg(r4 + q);
        size_t o = ob + (size_t)(3 + q * 4) * CH;
        out[o]          = v.x;
        out[o + CH]     = v.y;
        out[o + 2 * CH] = v.z;
        out[o + 3 * CH] = v.w;
    }
}

// ---------------------------------------------------------------------------
extern "C" void kernel_launch(void* const* d_in, const int* in_sizes, int n_in,
                              void* d_out, int out_size)
{
    const float* pc = (const float*)d_in[0];   // points_coords  (B,3,N)
    const float* cc = (const float*)d_in[1];   // centers_coords (B,3,M)
    const float* pf = (const float*)d_in[2];   // points_features(B,C,N)
    float* out = (float*)d_out;                // (B, 67, M, K)

    dim3 tgrid(NN / 64, BB);
    transpose_kernel<<<tgrid, 256>>>(pc, pf);
    scan_kernel<<<BB, 1024>>>();
    scatter_kernel<<<(BB * NN) / 256, 256>>>(pc);
    query_kernel<<<BB * MM / 8, 256>>>(cc, out);
}

// round 5
// speedup vs baseline: 2.2036x; 1.0491x over previous
#include <cuda_runtime.h>

#define BB 4
#define NN 16384
#define MM 2048
#define CC 64
#define KK 32
#define ROW 68            // xyz, pad, 64 features
#define R2C 0.01f
#define GC 10
#define NCELL 1000
#define IMAX 0x7fffffff

// Transposed rows for grouping gather: [b][n][0..2]=xyz, [3]=pad, [4..67]=features
__device__ __align__(16) float g_t[(size_t)BB * NN * ROW];
// Grid-binned points: (x, y, z, index-as-float-bits)
__device__ __align__(16) float4 g_bpt[BB * NN];
__device__ int g_cnt[BB * NCELL];          // zero-init; re-zeroed by scan_kernel
__device__ int g_start[BB * (NCELL + 1)];
__device__ int g_rk[BB * NN];              // per-point: cell*16384 + within-cell rank

__device__ __forceinline__ int cell_of(float x) {
    int c = (int)(x * 10.0f);
    return c < 0 ? 0 : (c > 9 ? 9 : c);
}

// ---------------------------------------------------------------------------
// K1: transpose (B,3,N)+(B,C,N) -> (B,N,68) rows; fused histogram + rank
// ---------------------------------------------------------------------------
__global__ void __launch_bounds__(256) transpose_kernel(
    const float* __restrict__ pc, const float* __restrict__ pf)
{
    __shared__ float tile[67][65];
    int b  = blockIdx.y;
    int n0 = blockIdx.x * 64;

    const float* src_c = pc + (size_t)b * 3 * NN;
    const float* src_f = pf + (size_t)b * CC * NN;

    // float4 loads along n
    for (int i = threadIdx.x; i < 67 * 16; i += 256) {
        int c = i >> 4, q = i & 15;
        const float* s = (c < 3) ? (src_c + (size_t)c * NN)
                                 : (src_f + (size_t)(c - 3) * NN);
        float4 v = *(const float4*)(s + n0 + q * 4);
        tile[c][q * 4 + 0] = v.x; tile[c][q * 4 + 1] = v.y;
        tile[c][q * 4 + 2] = v.z; tile[c][q * 4 + 3] = v.w;
    }
    __syncthreads();

    // fused histogram: atomic returns within-cell rank; save cell+rank per point
    if (threadIdx.x < 64) {
        int t = threadIdx.x;
        float x = tile[0][t], y = tile[1][t], z = tile[2][t];
        int cell = (cell_of(x) * GC + cell_of(y)) * GC + cell_of(z);
        int rank = atomicAdd(&g_cnt[b * NCELL + cell], 1);
        g_rk[b * NN + n0 + t] = cell * 16384 + rank;
    }

    // float4 stores along the 68-float row (row = 272B, 16B aligned)
    float* dst = g_t + ((size_t)b * NN + n0) * ROW;
    for (int i = threadIdx.x; i < 64 * 17; i += 256) {
        int nl = i / 17, q = i % 17;
        float4 v;
        if (q == 0) { v.x = tile[0][nl]; v.y = tile[1][nl]; v.z = tile[2][nl]; v.w = 0.0f; }
        else { v.x = tile[4*q-1][nl]; v.y = tile[4*q][nl]; v.z = tile[4*q+1][nl]; v.w = tile[4*q+2][nl]; }
        *(float4*)(dst + (size_t)nl * ROW + q * 4) = v;
    }
}

// ---------------------------------------------------------------------------
// K2: exclusive scan per batch (1 block/batch); re-zeroes g_cnt for next run
// ---------------------------------------------------------------------------
__global__ void __launch_bounds__(1024) scan_kernel()
{
    __shared__ int s[NCELL];
    int b = blockIdx.x, t = threadIdx.x;
    int myc = 0;
    if (t < NCELL) {
        myc = g_cnt[b * NCELL + t];
        g_cnt[b * NCELL + t] = 0;      // restore invariant for next replay
        s[t] = myc;
    }
    __syncthreads();
    for (int off = 1; off < NCELL; off <<= 1) {
        int v = 0;
        if (t < NCELL && t >= off) v = s[t - off];
        __syncthreads();
        if (t < NCELL) s[t] += v;
        __syncthreads();
    }
    if (t < NCELL) g_start[b * (NCELL + 1) + t] = s[t] - myc;
    if (t == 0)    g_start[b * (NCELL + 1) + NCELL] = NN;
}

// ---------------------------------------------------------------------------
// K3: scatter points into bins — atomic-free (rank precomputed in K1)
// ---------------------------------------------------------------------------
__global__ void __launch_bounds__(256) scatter_kernel(const float* __restrict__ pc)
{
    int t = blockIdx.x * 256 + threadIdx.x;
    if (t >= BB * NN) return;
    int b = t / NN, n = t % NN;
    int rk   = g_rk[t];
    int cell = rk >> 14;
    int rank = rk & 16383;
    int pos  = g_start[b * (NCELL + 1) + cell] + rank;
    const float* base = pc + (size_t)b * 3 * NN;
    float x = base[n], y = base[NN + n], z = base[2 * NN + n];
    g_bpt[b * NN + pos] = make_float4(x, y, z, __int_as_float(n));
}

// ---------------------------------------------------------------------------
// Warp bitonic helpers (32 elems across lanes)
// ---------------------------------------------------------------------------
__device__ __forceinline__ void bstage(int& h, int lane, int j, int k)
{
    int o = __shfl_xor_sync(0xffffffffu, h, j);
    bool asc   = (lane & k) == 0;
    bool lower = (lane & j) == 0;
    h = (lower == asc) ? min(h, o) : max(h, o);
}
__device__ __forceinline__ void sort32(int& h, int lane)
{
    bstage(h, lane, 1, 2);
    bstage(h, lane, 2, 4);  bstage(h, lane, 1, 4);
    bstage(h, lane, 4, 8);  bstage(h, lane, 2, 8);  bstage(h, lane, 1, 8);
    bstage(h, lane, 8, 16); bstage(h, lane, 4, 16); bstage(h, lane, 2, 16); bstage(h, lane, 1, 16);
    bstage(h, lane, 16, 32); bstage(h, lane, 8, 32); bstage(h, lane, 4, 32);
    bstage(h, lane, 2, 32);  bstage(h, lane, 1, 32);
}
__device__ __forceinline__ void clean32(int& h, int lane)
{
    #pragma unroll
    for (int j = 16; j >= 1; j >>= 1) {
        int o = __shfl_xor_sync(0xffffffffu, h, j);
        h = ((lane & j) == 0) ? min(h, o) : max(h, o);
    }
}
__device__ __forceinline__ void merge_min32(int& a, int b, int lane)
{
    int br = __shfl_sync(0xffffffffu, b, 31 ^ lane);  // b reversed
    a = min(a, br);                                   // bitonic
    clean32(a, lane);
}

// ---------------------------------------------------------------------------
// K4: warp-per-center grid ball query + top-32 select + fused grouping
// ---------------------------------------------------------------------------
__global__ void __launch_bounds__(256, 4) query_kernel(
    const float* __restrict__ cc, float* __restrict__ out)
{
    __shared__ int hits[8][128];
    int wib  = threadIdx.x >> 5;
    int lane = threadIdx.x & 31;
    int* hb  = hits[wib];

    int gw = blockIdx.x * 8 + wib;
    int b = gw / MM;
    int m = gw % MM;

    const float* cb = cc + (size_t)b * 3 * MM;
    float cx = cb[m], cy = cb[MM + m], cz = cb[2 * MM + m];
    float c2 = __fadd_rn(__fadd_rn(__fmul_rn(cx, cx), __fmul_rn(cy, cy)),
                         __fmul_rn(cz, cz));

    int ci = cell_of(cx), cj = cell_of(cy), ck = cell_of(cz);
    int i0 = max(ci - 1, 0), i1 = min(ci + 1, 9);
    int j0 = max(cj - 1, 0), j1 = min(cj + 1, 9);
    int k0 = max(ck - 1, 0), k1 = min(ck + 1, 9);

    const float4* bpt = g_bpt + (size_t)b * NN;
    const int* st     = g_start + b * (NCELL + 1);

    unsigned below = (1u << lane) - 1u;
    int cnt = 0;

    for (int i = i0; i <= i1; i++) {
        for (int j = j0; j <= j1; j++) {
            int cbase = (i * GC + j) * GC;
            int s = st[cbase + k0];
            int e = st[cbase + k1 + 1];     // k-range contiguous in bins
            for (int p0 = s; p0 < e; p0 += 32) {
                int p = p0 + lane;
                bool hit = false;
                float4 v;
                if (p < e) {
                    v = __ldg(bpt + p);
                    // reference p2: (x*x + y*y) + z*z, individually rounded
                    float p2 = __fadd_rn(__fadd_rn(__fmul_rn(v.x, v.x),
                                                   __fmul_rn(v.y, v.y)),
                                         __fmul_rn(v.z, v.z));
                    // reference inner: cuBLAS k=3 FMA chain
                    float inner = __fmaf_rn(cz, v.z,
                                  __fmaf_rn(cy, v.y, __fmul_rn(cx, v.x)));
                    float d2 = __fsub_rn(__fadd_rn(c2, p2),
                                         __fmul_rn(2.0f, inner));
                    hit = d2 < R2C;
                }
                unsigned wm = __ballot_sync(0xffffffffu, hit);
                if (hit) {
                    int rank = cnt + __popc(wm & below);
                    if (rank < 128) hb[rank] = __float_as_int(v.w);
                }
                cnt += __popc(wm);
            }
        }
    }
    __syncwarp();

    // load up to 128 collected hits (pads = IMAX)
    int h0 = (lane      < cnt) ? hb[lane]      : IMAX;
    int h1 = (lane + 32 < cnt) ? hb[lane + 32] : IMAX;
    int h2 = (lane + 64 < cnt) ? hb[lane + 64] : IMAX;
    int h3 = (lane + 96 < cnt) ? hb[lane + 96] : IMAX;

    // top-32 smallest (ascending) into h0
    sort32(h0, lane); sort32(h1, lane); sort32(h2, lane); sort32(h3, lane);
    merge_min32(h0, h1, lane);
    merge_min32(h2, h3, lane);
    merge_min32(h0, h2, lane);

    int myidx = h0;
    int first = __shfl_sync(0xffffffffu, h0, 0);
    if (first == IMAX) first = 0;
    if (myidx == IMAX) myidx = first;

    // ---- fused grouping: lane = output slot k; batched loads for MLP ----
    const float4* r4 = (const float4*)(g_t + ((size_t)b * NN + myidx) * ROW);

    const size_t CH = (size_t)MM * KK;
    size_t ob = (((size_t)b * 67) * MM + m) * KK + lane;

    {
        float4 w[9];
        #pragma unroll
        for (int q = 0; q < 9; q++) w[q] = __ldg(r4 + q);   // w[0] = xyz,pad
        out[ob]          = __fsub_rn(w[0].x, cx);
        out[ob + CH]     = __fsub_rn(w[0].y, cy);
        out[ob + 2 * CH] = __fsub_rn(w[0].z, cz);
        #pragma unroll
        for (int q = 1; q < 9; q++) {
            size_t o = ob + (size_t)(4 * q - 1) * CH;       // channels 4q-1..4q+2
            out[o]          = w[q].x;
            out[o + CH]     = w[q].y;
            out[o + 2 * CH] = w[q].z;
            out[o + 3 * CH] = w[q].w;
        }
    }
    {
        float4 u[8];
        #pragma unroll
        for (int q = 0; q < 8; q++) u[q] = __ldg(r4 + 9 + q);
        #pragma unroll
        for (int q = 0; q < 8; q++) {
            size_t o = ob + (size_t)(35 + 4 * q) * CH;      // channels 35..66
            out[o]          = u[q].x;
            out[o + CH]     = u[q].y;
            out[o + 2 * CH] = u[q].z;
            out[o + 3 * CH] = u[q].w;
        }
    }
}

// ---------------------------------------------------------------------------
extern "C" void kernel_launch(void* const* d_in, const int* in_sizes, int n_in,
                              void* d_out, int out_size)
{
    const float* pc = (const float*)d_in[0];   // points_coords  (B,3,N)
    const float* cc = (const float*)d_in[1];   // centers_coords (B,3,M)
    const float* pf = (const float*)d_in[2];   // points_features(B,C,N)
    float* out = (float*)d_out;                // (B, 67, M, K)

    dim3 tgrid(NN / 64, BB);
    transpose_kernel<<<tgrid, 256>>>(pc, pf);
    scan_kernel<<<BB, 1024>>>();
    scatter_kernel<<<(BB * NN) / 256, 256>>>(pc);
    query_kernel<<<BB * MM / 8, 256>>>(cc, out);
}